// round 13
// baseline (speedup 1.0000x reference)
#include <cuda_runtime.h>
#include <cuda_bf16.h>
#include <cstdint>

#define D 128
#define NG 1024
#define MAXN 100000
#define MAXE 1600000
#define BN_EPS 1e-5f

// ---------------- scratch (static device memory) ----------------------------
__device__ float g_agg[MAXN * D];
__device__ float g_xa[MAXN * D];
__device__ float g_xb[MAXN * D];
__device__ float g_W1p[3 * D * D];
__device__ float g_b1p[3 * D];
__device__ float g_pool[NG * D];
__device__ float g_hid[NG * D];
// CSR
__device__ int g_deg[MAXN];
__device__ int g_off[MAXN + 1];
__device__ int g_cur[MAXN];
__device__ int g_col[MAXE];
__device__ int g_bsums[256];
// pre-split weights, [n][k] layout (col-major B for mma .row.col):
// mats: 0..2 = BN-folded W1, 3..5 = W2, 6 = head W1, 7 = head W2
__device__ __nv_bfloat16 g_Wt_hi[8 * D * D];
__device__ __nv_bfloat16 g_Wt_lo[8 * D * D];

// ---------------- helpers ----------------------------------------------------
__device__ __forceinline__ uint32_t smem_u32(const void* p) {
    uint32_t a;
    asm("{ .reg .u64 t; cvta.to.shared.u64 t, %1; cvt.u32.u64 %0, t; }"
        : "=r"(a) : "l"(p));
    return a;
}

__device__ __forceinline__ void mma16816(float* c,
                                         uint32_t a0, uint32_t a1, uint32_t a2, uint32_t a3,
                                         uint32_t b0, uint32_t b1) {
    asm volatile("mma.sync.aligned.m16n8k16.row.col.f32.bf16.bf16.f32 "
                 "{%0,%1,%2,%3}, {%4,%5,%6,%7}, {%8,%9}, {%0,%1,%2,%3};"
                 : "+f"(c[0]), "+f"(c[1]), "+f"(c[2]), "+f"(c[3])
                 : "r"(a0), "r"(a1), "r"(a2), "r"(a3), "r"(b0), "r"(b1));
}

// smem tile geometry: pitch 136 bf16 (272 B)
#define PITCH 136
#define TILE_B (128 * PITCH * 2)          // 34816 bytes
#define SA_HI 0
#define SA_LO TILE_B
#define SB_HI (2 * TILE_B)
#define SB_LO (3 * TILE_B)
#define S_B1 (4 * TILE_B)
#define S_B2 (4 * TILE_B + 512)
#define GEMM_SMEM (4 * TILE_B + 1024)

// stage pre-split W matrix `mat` into SB (pitched)
__device__ __forceinline__ void stage_W(char* smp, int mat, int t) {
    const float4* bh = (const float4*)g_Wt_hi + (size_t)mat * 2048;
    const float4* bl = (const float4*)g_Wt_lo + (size_t)mat * 2048;
#pragma unroll
    for (int it = 0; it < 8; it++) {
        int idx = it * 256 + t;        // nn = idx>>4, c16 = idx&15
        int off = (idx >> 4) * (PITCH * 2) + (idx & 15) * 16;
        *(float4*)(smp + SB_HI + off) = __ldg(bh + idx);
        *(float4*)(smp + SB_LO + off) = __ldg(bl + idx);
    }
}

// MMA over SA x SB -> acc[16][4] (3-term bf16 split).
// B fragments for TWO adjacent nt tiles loaded per ldmatrix.x4:
// lane octet g: (g>>1) selects nt of pair, (g&1) selects k-half.
__device__ __forceinline__ void do_mma(uint32_t base, int lane, int m0, float acc[16][4]) {
#pragma unroll
    for (int i = 0; i < 16; i++)
#pragma unroll
        for (int j = 0; j < 4; j++) acc[i][j] = 0.f;
    int amat = lane >> 3;
    int arow = m0 + (lane & 7) + ((amat & 1) << 3);
    int akof = (amat >> 1) << 3;
    int g = lane >> 3;
    int brow = (lane & 7) + ((g >> 1) << 3);     // row within the 16-row nt pair
    int bkof = (g & 1) << 3;                     // k offset 0 / 8
    uint32_t bbase = base + SB_HI + brow * (PITCH * 2) + bkof * 2;
#pragma unroll
    for (int k16 = 0; k16 < 8; k16++) {
        int kb = k16 * 16;
        uint32_t ah0, ah1, ah2, ah3, al0, al1, al2, al3;
        uint32_t aaddr = base + SA_HI + arow * (PITCH * 2) + (kb + akof) * 2;
        asm volatile("ldmatrix.sync.aligned.m8n8.x4.shared.b16 {%0,%1,%2,%3}, [%4];"
                     : "=r"(ah0), "=r"(ah1), "=r"(ah2), "=r"(ah3) : "r"(aaddr));
        asm volatile("ldmatrix.sync.aligned.m8n8.x4.shared.b16 {%0,%1,%2,%3}, [%4];"
                     : "=r"(al0), "=r"(al1), "=r"(al2), "=r"(al3)
                     : "r"(aaddr + (uint32_t)TILE_B));
#pragma unroll
        for (int ntp = 0; ntp < 8; ntp++) {
            uint32_t bh0, bh1, bh2, bh3, bl0, bl1, bl2, bl3;
            uint32_t baddr = bbase + ntp * 16 * (PITCH * 2) + kb * 2;
            asm volatile("ldmatrix.sync.aligned.m8n8.x4.shared.b16 {%0,%1,%2,%3}, [%4];"
                         : "=r"(bh0), "=r"(bh1), "=r"(bh2), "=r"(bh3) : "r"(baddr));
            asm volatile("ldmatrix.sync.aligned.m8n8.x4.shared.b16 {%0,%1,%2,%3}, [%4];"
                         : "=r"(bl0), "=r"(bl1), "=r"(bl2), "=r"(bl3)
                         : "r"(baddr + (uint32_t)TILE_B));
            float* c0 = acc[2 * ntp];
            float* c1 = acc[2 * ntp + 1];
            mma16816(c0, ah0, ah1, ah2, ah3, bh0, bh1);
            mma16816(c1, ah0, ah1, ah2, ah3, bh2, bh3);
            mma16816(c0, ah0, ah1, ah2, ah3, bl0, bl1);
            mma16816(c1, ah0, ah1, ah2, ah3, bl2, bl3);
            mma16816(c0, al0, al1, al2, al3, bh0, bh1);
            mma16816(c1, al0, al1, al2, al3, bh2, bh3);
        }
    }
}

__device__ __forceinline__ uint32_t split2(float v0, float v1, uint32_t& lo_out) {
    __nv_bfloat16 h0 = __float2bfloat16(v0), h1 = __float2bfloat16(v1);
    __nv_bfloat16 l0 = __float2bfloat16(v0 - __bfloat162float(h0));
    __nv_bfloat16 l1 = __float2bfloat16(v1 - __bfloat162float(h1));
    lo_out = ((uint32_t)__bfloat16_as_ushort(l1) << 16) | __bfloat16_as_ushort(l0);
    return ((uint32_t)__bfloat16_as_ushort(h1) << 16) | __bfloat16_as_ushort(h0);
}

// ---------------- fold BN into W1/b1 ----------------------------------------
__global__ void fold_bn_kernel(const float* __restrict__ W1,
                               const float* __restrict__ b1,
                               const float* __restrict__ gamma,
                               const float* __restrict__ beta,
                               const float* __restrict__ mean,
                               const float* __restrict__ var) {
    int k = blockIdx.x;
    int l = blockIdx.y;
    int c = threadIdx.x;
    float s = rsqrtf(var[l * D + c] + BN_EPS) * gamma[l * D + c];
    g_W1p[(l * D + k) * D + c] = W1[(l * D + k) * D + c] * s;
    if (k == 0)
        g_b1p[l * D + c] = (b1[l * D + c] - mean[l * D + c]) * s + beta[l * D + c];
}

// ---------------- pre-split weights: Wt[n][k] = W[k][n], hi/lo bf16 ----------
__global__ void prep_w_kernel(const float* __restrict__ W2,
                              const float* __restrict__ hW1,
                              const float* __restrict__ hW2) {
    int idx = blockIdx.x * 256 + threadIdx.x;   // 0..16383
    int m = blockIdx.y;                          // 0..7
    int nn = idx & 127;
    int k  = idx >> 7;
    float w;
    if (m < 3)      w = g_W1p[m * D * D + k * D + nn];
    else if (m < 6) w = W2[(m - 3) * D * D + k * D + nn];
    else if (m == 6) w = hW1[k * D + nn];
    else             w = hW2[k * D + nn];
    __nv_bfloat16 hi = __float2bfloat16(w);
    float rem = w - __bfloat162float(hi);
    int off = m * D * D + nn * D + k;           // [mat][n][k]
    g_Wt_hi[off] = hi;
    g_Wt_lo[off] = __float2bfloat16(rem);
}

// ---------------- CSR build --------------------------------------------------
__global__ void zero_deg(int* deg, int n) {
    int i = blockIdx.x * 256 + threadIdx.x;
    if (i < n) deg[i] = 0;
}

__global__ void hist_kernel(const int* __restrict__ ei, int* deg, int nE) {
    int e = blockIdx.x * 256 + threadIdx.x;
    if (e < nE) atomicAdd(&deg[__ldg(ei + nE + e)], 1);
}

__global__ void scan1(const int* __restrict__ deg, int* off, int* bsums, int n) {
    __shared__ int warpsum[16];
    int t = threadIdx.x;
    int i = blockIdx.x * 512 + t;
    int v = (i < n) ? deg[i] : 0;
    int lane = t & 31, w = t >> 5;
    int s = v;
#pragma unroll
    for (int o = 1; o < 32; o <<= 1) {
        int u = __shfl_up_sync(0xffffffffu, s, o);
        if (lane >= o) s += u;
    }
    if (lane == 31) warpsum[w] = s;
    __syncthreads();
    if (w == 0) {
        int ws = (lane < 16) ? warpsum[lane] : 0;
#pragma unroll
        for (int o = 1; o < 16; o <<= 1) {
            int u = __shfl_up_sync(0xffffffffu, ws, o);
            if (lane >= o) ws += u;
        }
        if (lane < 16) warpsum[lane] = ws;
    }
    __syncthreads();
    int base = (w > 0) ? warpsum[w - 1] : 0;
    if (i < n) off[i] = base + s - v;
    if (t == 0) bsums[blockIdx.x] = warpsum[15];
}

__global__ void scan2(int* bsums, int nb) {
    __shared__ int ws[8];
    int t = threadIdx.x, lane = t & 31, w = t >> 5;
    int v = (t < nb) ? bsums[t] : 0;
    int s = v;
#pragma unroll
    for (int o = 1; o < 32; o <<= 1) {
        int u = __shfl_up_sync(0xffffffffu, s, o);
        if (lane >= o) s += u;
    }
    if (lane == 31) ws[w] = s;
    __syncthreads();
    if (w == 0 && lane < 8) {
        int a = ws[lane];
#pragma unroll
        for (int o = 1; o < 8; o <<= 1) {
            int u = __shfl_up_sync(0xffu, a, o);
            if (lane >= o) a += u;
        }
        ws[lane] = a;
    }
    __syncthreads();
    int base = (w > 0) ? ws[w - 1] : 0;
    if (t < nb) bsums[t] = base + s - v;
}

__global__ void scan3(int* off, const int* __restrict__ bsums, int* cur, int n, int nE) {
    int i = blockIdx.x * 256 + threadIdx.x;
    if (i < n) {
        int v = off[i] + bsums[i >> 9];
        off[i] = v;
        cur[i] = v;
    }
    if (i == 0) off[n] = nE;
}

__global__ void fill_csr(const int* __restrict__ ei, int* cur, int* col, int nE) {
    int e = blockIdx.x * 256 + threadIdx.x;
    if (e >= nE) return;
    int s = __ldg(ei + e);
    int d = __ldg(ei + nE + e);
    int p = atomicAdd(&cur[d], 1);
    col[p] = s;
}

// ---------------- aggregation: agg[i] = x[i] + sum_{j in N(i)} x[j] ---------
__global__ void gather_agg(const float* __restrict__ x,
                           const int* __restrict__ off,
                           const int* __restrict__ col,
                           float* __restrict__ agg, int n) {
    int node = blockIdx.x * 8 + (threadIdx.x >> 5);
    if (node >= n) return;
    int lane = threadIdx.x & 31;
    int beg = __ldg(off + node), end = __ldg(off + node + 1);
    float4 acc = __ldg((const float4*)x + (long long)node * 32 + lane);
    int e = beg;
    for (; e + 3 < end; e += 4) {
        int s0 = __ldg(col + e), s1 = __ldg(col + e + 1);
        int s2 = __ldg(col + e + 2), s3 = __ldg(col + e + 3);
        float4 v0 = __ldg((const float4*)x + (long long)s0 * 32 + lane);
        float4 v1 = __ldg((const float4*)x + (long long)s1 * 32 + lane);
        float4 v2 = __ldg((const float4*)x + (long long)s2 * 32 + lane);
        float4 v3 = __ldg((const float4*)x + (long long)s3 * 32 + lane);
        acc.x += v0.x + v1.x + v2.x + v3.x;
        acc.y += v0.y + v1.y + v2.y + v3.y;
        acc.z += v0.z + v1.z + v2.z + v3.z;
        acc.w += v0.w + v1.w + v2.w + v3.w;
    }
    for (; e < end; e++) {
        int s0 = __ldg(col + e);
        float4 v0 = __ldg((const float4*)x + (long long)s0 * 32 + lane);
        acc.x += v0.x; acc.y += v0.y; acc.z += v0.z; acc.w += v0.w;
    }
    ((float4*)agg)[(long long)node * 32 + lane] = acc;
}

// ---------------- pooling (batch is sorted -> segmented reduction) ----------
__global__ void zero_kernel(float4* __restrict__ p, int n4) {
    int i = blockIdx.x * blockDim.x + threadIdx.x;
    if (i < n4) p[i] = make_float4(0.f, 0.f, 0.f, 0.f);
}

__global__ void pool_nodes(const float* __restrict__ x,
                           const int* __restrict__ batch,
                           float* __restrict__ g, int n) {
    int w = blockIdx.x * 8 + (threadIdx.x >> 5);   // warp id: 8 nodes each
    int lane = threadIdx.x & 31;
    int i0 = w * 8;
    if (i0 >= n) return;
    int iend = min(i0 + 8, n);
    int curb = __ldg(batch + i0);
    float4 acc = make_float4(0.f, 0.f, 0.f, 0.f);
    for (int i = i0; i < iend; i++) {
        int b = __ldg(batch + i);
        if (b != curb) {
            const float4* dp = (const float4*)g + (long long)curb * 32 + lane;
            asm volatile("red.global.add.v4.f32 [%0], {%1, %2, %3, %4};"
                         :: "l"(dp), "f"(acc.x), "f"(acc.y), "f"(acc.z), "f"(acc.w)
                         : "memory");
            acc = make_float4(0.f, 0.f, 0.f, 0.f);
            curb = b;
        }
        float4 v = __ldg((const float4*)x + (long long)i * 32 + lane);
        acc.x += v.x; acc.y += v.y; acc.z += v.z; acc.w += v.w;
    }
    const float4* dp = (const float4*)g + (long long)curb * 32 + lane;
    asm volatile("red.global.add.v4.f32 [%0], {%1, %2, %3, %4};"
                 :: "l"(dp), "f"(acc.x), "f"(acc.y), "f"(acc.z), "f"(acc.w)
                 : "memory");
}

// ---------------- fused GEMM pair: C = relu(relu(A@W1+b1)@W2+b2) ------------
__global__ __launch_bounds__(256, 1) void gemm_pair(
    const float* __restrict__ A, int mat1, int mat2,
    const float* __restrict__ bias1, const float* __restrict__ bias2,
    float* __restrict__ C, int n) {
    extern __shared__ char smp[];
    uint32_t base = smem_u32(smp);
    int t = threadIdx.x;
    int wid = t >> 5;
    int lane = t & 31;
    int row0 = blockIdx.x * 128;
    int m0 = wid * 16;

    // stage A (f32 -> split bf16)
#pragma unroll
    for (int it = 0; it < 16; it++) {
        int idx = it * 256 + t;
        int row = idx >> 5;
        int k4 = idx & 31;
        float4 v = make_float4(0.f, 0.f, 0.f, 0.f);
        if (row0 + row < n) v = __ldg((const float4*)A + (long long)(row0 + row) * 32 + k4);
        uint2 hp, lp;
        hp.x = split2(v.x, v.y, lp.x);
        hp.y = split2(v.z, v.w, lp.y);
        int off = row * (PITCH * 2) + k4 * 8;
        *(uint2*)(smp + SA_HI + off) = hp;
        *(uint2*)(smp + SA_LO + off) = lp;
    }
    stage_W(smp, mat1, t);
    if (t < 32) {
        ((float4*)(smp + S_B1))[t] = __ldg((const float4*)bias1 + t);
        ((float4*)(smp + S_B2))[t] = __ldg((const float4*)bias2 + t);
    }
    __syncthreads();

    // MMA1
    float acc[16][4];
    do_mma(base, lane, m0, acc);
    __syncthreads();

    // h1 = relu(acc + bias1) -> re-split into SA;  restage W2
    {
        const float* b1s = (const float*)(smp + S_B1);
        int rA = m0 + (lane >> 2);
        int cq = (lane & 3) * 2;
#pragma unroll
        for (int nt = 0; nt < 16; nt++) {
            int cl = nt * 8 + cq;
            float b0 = b1s[cl], b1v = b1s[cl + 1];
            float v0 = fmaxf(acc[nt][0] + b0, 0.f), v1 = fmaxf(acc[nt][1] + b1v, 0.f);
            float v2 = fmaxf(acc[nt][2] + b0, 0.f), v3 = fmaxf(acc[nt][3] + b1v, 0.f);
            uint32_t lo0, lo1;
            uint32_t hi0 = split2(v0, v1, lo0);
            uint32_t hi1 = split2(v2, v3, lo1);
            int o0 = rA * (PITCH * 2) + cl * 2;
            int o1 = (rA + 8) * (PITCH * 2) + cl * 2;
            *(uint32_t*)(smp + SA_HI + o0) = hi0;
            *(uint32_t*)(smp + SA_LO + o0) = lo0;
            *(uint32_t*)(smp + SA_HI + o1) = hi1;
            *(uint32_t*)(smp + SA_LO + o1) = lo1;
        }
    }
    stage_W(smp, mat2, t);
    __syncthreads();

    // MMA2
    do_mma(base, lane, m0, acc);

    // epilogue: out = relu(acc + bias2)
    {
        const float* b2s = (const float*)(smp + S_B2);
        int r0 = row0 + m0 + (lane >> 2);
        int cq = (lane & 3) * 2;
#pragma unroll
        for (int nt = 0; nt < 16; nt++) {
            int cl = nt * 8 + cq;
            float b0 = b2s[cl], b1v = b2s[cl + 1];
            float2 v0 = make_float2(fmaxf(acc[nt][0] + b0, 0.f), fmaxf(acc[nt][1] + b1v, 0.f));
            float2 v1 = make_float2(fmaxf(acc[nt][2] + b0, 0.f), fmaxf(acc[nt][3] + b1v, 0.f));
            if (r0 < n)     *(float2*)(C + (long long)r0 * D + cl) = v0;
            if (r0 + 8 < n) *(float2*)(C + (long long)(r0 + 8) * D + cl) = v1;
        }
    }
}

// ---------------- standalone mma GEMM (head) --------------------------------
__global__ __launch_bounds__(256, 1) void gemm_tc(
    const float* __restrict__ A, int mat,
    const float* __restrict__ bias, float* __restrict__ C, int n, int relu) {
    extern __shared__ char smp[];
    uint32_t base = smem_u32(smp);
    int t = threadIdx.x;
    int wid = t >> 5;
    int lane = t & 31;
    int row0 = blockIdx.x * 128;

#pragma unroll
    for (int it = 0; it < 16; it++) {
        int idx = it * 256 + t;
        int row = idx >> 5;
        int k4 = idx & 31;
        float4 v = make_float4(0.f, 0.f, 0.f, 0.f);
        if (row0 + row < n) v = __ldg((const float4*)A + (long long)(row0 + row) * 32 + k4);
        uint2 hp, lp;
        hp.x = split2(v.x, v.y, lp.x);
        hp.y = split2(v.z, v.w, lp.y);
        int off = row * (PITCH * 2) + k4 * 8;
        *(uint2*)(smp + SA_HI + off) = hp;
        *(uint2*)(smp + SA_LO + off) = lp;
    }
    stage_W(smp, mat, t);
    if (t < 32) ((float4*)(smp + S_B1))[t] = __ldg((const float4*)bias + t);
    __syncthreads();

    float acc[16][4];
    do_mma(base, lane, wid * 16, acc);

    const float* bias_s = (const float*)(smp + S_B1);
    int r0 = row0 + wid * 16 + (lane >> 2);
    int cq = (lane & 3) * 2;
#pragma unroll
    for (int nt = 0; nt < 16; nt++) {
        int cl = nt * 8 + cq;
        float b0 = bias_s[cl], b1v = bias_s[cl + 1];
        float2 v0 = make_float2(acc[nt][0] + b0, acc[nt][1] + b1v);
        float2 v1 = make_float2(acc[nt][2] + b0, acc[nt][3] + b1v);
        if (relu) {
            v0.x = fmaxf(v0.x, 0.f); v0.y = fmaxf(v0.y, 0.f);
            v1.x = fmaxf(v1.x, 0.f); v1.y = fmaxf(v1.y, 0.f);
        }
        if (r0 < n)     *(float2*)(C + (long long)r0 * D + cl) = v0;
        if (r0 + 8 < n) *(float2*)(C + (long long)(r0 + 8) * D + cl) = v1;
    }
}

// ---------------- launch -----------------------------------------------------
extern "C" void kernel_launch(void* const* d_in, const int* in_sizes, int n_in,
                              void* d_out, int out_size) {
    const float* x        = (const float*)d_in[0];
    const int*   ei       = (const int*)d_in[1];      // int32 (JAX x64 disabled)
    const int*   batch    = (const int*)d_in[2];      // int32
    const float* W1       = (const float*)d_in[3];
    const float* b1       = (const float*)d_in[4];
    const float* gamma    = (const float*)d_in[5];
    const float* beta     = (const float*)d_in[6];
    const float* mean     = (const float*)d_in[7];
    const float* var      = (const float*)d_in[8];
    const float* W2       = (const float*)d_in[9];
    const float* b2       = (const float*)d_in[10];
    const float* hW1      = (const float*)d_in[11];
    const float* hb1      = (const float*)d_in[12];
    const float* hW2      = (const float*)d_in[13];
    const float* hb2      = (const float*)d_in[14];

    int n  = in_sizes[0] / D;
    int nE = in_sizes[1] / 2;

    float *agg, *xa, *xb, *b1p, *pool, *hid;
    int *deg, *off, *cur, *col, *bsums;
    cudaGetSymbolAddress((void**)&agg,  g_agg);
    cudaGetSymbolAddress((void**)&xa,   g_xa);
    cudaGetSymbolAddress((void**)&xb,   g_xb);
    cudaGetSymbolAddress((void**)&b1p,  g_b1p);
    cudaGetSymbolAddress((void**)&pool, g_pool);
    cudaGetSymbolAddress((void**)&hid,  g_hid);
    cudaGetSymbolAddress((void**)&deg,  g_deg);
    cudaGetSymbolAddress((void**)&off,  g_off);
    cudaGetSymbolAddress((void**)&cur,  g_cur);
    cudaGetSymbolAddress((void**)&col,  g_col);
    cudaGetSymbolAddress((void**)&bsums, g_bsums);

    cudaFuncSetAttribute(gemm_pair, cudaFuncAttributeMaxDynamicSharedMemorySize, GEMM_SMEM);
    cudaFuncSetAttribute(gemm_tc, cudaFuncAttributeMaxDynamicSharedMemorySize, GEMM_SMEM);

    int gemmGrid = (n + 127) / 128;
    int nb = (n + 511) / 512;

    // prep: BN fold, weight split, CSR build
    fold_bn_kernel<<<dim3(D, 3), D>>>(W1, b1, gamma, beta, mean, var);
    prep_w_kernel<<<dim3(64, 8), 256>>>(W2, hW1, hW2);
    zero_deg<<<(n + 255) / 256, 256>>>(deg, n);
    hist_kernel<<<(nE + 255) / 256, 256>>>(ei, deg, nE);
    scan1<<<nb, 512>>>(deg, off, bsums, n);
    scan2<<<1, 256>>>(bsums, nb);
    scan3<<<(n + 255) / 256, 256>>>(off, bsums, cur, n, nE);
    fill_csr<<<(nE + 255) / 256, 256>>>(ei, cur, col, nE);

    const float* xin = x;
    float* outs[3] = {xa, xb, xa};
    for (int l = 0; l < 3; l++) {
        gather_agg<<<(n + 7) / 8, 256>>>(xin, off, col, agg, n);
        gemm_pair<<<gemmGrid, 256, GEMM_SMEM>>>(agg, l, 3 + l,
                                                b1p + l * D, b2 + l * D,
                                                outs[l], n);
        xin = outs[l];
    }

    zero_kernel<<<(NG * 32 + 255) / 256, 256>>>((float4*)pool, NG * 32);
    pool_nodes<<<(n + 63) / 64, 256>>>(xin, batch, pool, n);
    gemm_tc<<<NG / 128, 256, GEMM_SMEM>>>(pool, 6, hb1, hid, NG, 1);
    gemm_tc<<<NG / 128, 256, GEMM_SMEM>>>(hid, 7, hb2, (float*)d_out, NG, 0);
}

// round 15
// speedup vs baseline: 1.0705x; 1.0705x over previous
#include <cuda_runtime.h>
#include <cuda_bf16.h>
#include <cstdint>

#define D 128
#define NG 1024
#define MAXN 100000
#define MAXE 1600000
#define BN_EPS 1e-5f

// ---------------- scratch (static device memory) ----------------------------
__device__ float g_agg[MAXN * D];
__device__ float g_xa[MAXN * D];
__device__ float g_xb[MAXN * D];
__device__ float g_W1p[3 * D * D];
__device__ float g_b1p[3 * D];
__device__ float g_pool[NG * D];
__device__ float g_hid[NG * D];
// CSR
__device__ int g_deg[MAXN];
__device__ int g_off[MAXN + 1];
__device__ int g_cur[MAXN];
__device__ int g_col[MAXE];
__device__ int g_bsums[256];
// pre-split weights, [n][k] layout (col-major B for mma .row.col):
// mats: 0..2 = BN-folded W1, 3..5 = W2, 6 = head W1, 7 = head W2
__device__ __nv_bfloat16 g_Wt_hi[8 * D * D];
__device__ __nv_bfloat16 g_Wt_lo[8 * D * D];

// ---------------- helpers ----------------------------------------------------
__device__ __forceinline__ uint32_t smem_u32(const void* p) {
    uint32_t a;
    asm("{ .reg .u64 t; cvta.to.shared.u64 t, %1; cvt.u32.u64 %0, t; }"
        : "=r"(a) : "l"(p));
    return a;
}

__device__ __forceinline__ void mma16816(float* c,
                                         uint32_t a0, uint32_t a1, uint32_t a2, uint32_t a3,
                                         uint32_t b0, uint32_t b1) {
    asm volatile("mma.sync.aligned.m16n8k16.row.col.f32.bf16.bf16.f32 "
                 "{%0,%1,%2,%3}, {%4,%5,%6,%7}, {%8,%9}, {%0,%1,%2,%3};"
                 : "+f"(c[0]), "+f"(c[1]), "+f"(c[2]), "+f"(c[3])
                 : "r"(a0), "r"(a1), "r"(a2), "r"(a3), "r"(b0), "r"(b1));
}

// smem tile geometry: pitch 136 bf16 (272 B); BM=64 rows, BN(K)=128
#define PITCH 136
#define ATILE_B (64 * PITCH * 2)           // 17408 bytes (A: 64 rows)
#define BTILE_B (128 * PITCH * 2)          // 34816 bytes (B: 128 n-rows)
#define SA_HI 0
#define SA_LO ATILE_B
#define SB_HI (2 * ATILE_B)
#define SB_LO (2 * ATILE_B + BTILE_B)
#define S_B1 (2 * ATILE_B + 2 * BTILE_B)
#define S_B2 (S_B1 + 512)
#define GEMM_SMEM (S_B2 + 512)             // 105472 B -> 2 CTAs/SM

// stage pre-split W matrix `mat` into SB (pitched), 128 threads
__device__ __forceinline__ void stage_W(char* smp, int mat, int t) {
    const float4* bh = (const float4*)g_Wt_hi + (size_t)mat * 2048;
    const float4* bl = (const float4*)g_Wt_lo + (size_t)mat * 2048;
#pragma unroll
    for (int it = 0; it < 16; it++) {
        int idx = it * 128 + t;        // nn = idx>>4, c16 = idx&15
        int off = (idx >> 4) * (PITCH * 2) + (idx & 15) * 16;
        *(float4*)(smp + SB_HI + off) = __ldg(bh + idx);
        *(float4*)(smp + SB_LO + off) = __ldg(bl + idx);
    }
}

// MMA over SA(64 rows) x SB(128 n) -> acc[16][4] (3-term bf16 split).
// B fragments for TWO adjacent nt tiles per ldmatrix.x4.
__device__ __forceinline__ void do_mma(uint32_t base, int lane, int m0, float acc[16][4]) {
#pragma unroll
    for (int i = 0; i < 16; i++)
#pragma unroll
        for (int j = 0; j < 4; j++) acc[i][j] = 0.f;
    int amat = lane >> 3;
    int arow = m0 + (lane & 7) + ((amat & 1) << 3);
    int akof = (amat >> 1) << 3;
    int g = lane >> 3;
    int brow = (lane & 7) + ((g >> 1) << 3);
    int bkof = (g & 1) << 3;
    uint32_t bbase = base + SB_HI + brow * (PITCH * 2) + bkof * 2;
#pragma unroll
    for (int k16 = 0; k16 < 8; k16++) {
        int kb = k16 * 16;
        uint32_t ah0, ah1, ah2, ah3, al0, al1, al2, al3;
        uint32_t aaddr = base + SA_HI + arow * (PITCH * 2) + (kb + akof) * 2;
        asm volatile("ldmatrix.sync.aligned.m8n8.x4.shared.b16 {%0,%1,%2,%3}, [%4];"
                     : "=r"(ah0), "=r"(ah1), "=r"(ah2), "=r"(ah3) : "r"(aaddr));
        asm volatile("ldmatrix.sync.aligned.m8n8.x4.shared.b16 {%0,%1,%2,%3}, [%4];"
                     : "=r"(al0), "=r"(al1), "=r"(al2), "=r"(al3)
                     : "r"(aaddr + (uint32_t)ATILE_B));
#pragma unroll
        for (int ntp = 0; ntp < 8; ntp++) {
            uint32_t bh0, bh1, bh2, bh3, bl0, bl1, bl2, bl3;
            uint32_t baddr = bbase + ntp * 16 * (PITCH * 2) + kb * 2;
            asm volatile("ldmatrix.sync.aligned.m8n8.x4.shared.b16 {%0,%1,%2,%3}, [%4];"
                         : "=r"(bh0), "=r"(bh1), "=r"(bh2), "=r"(bh3) : "r"(baddr));
            asm volatile("ldmatrix.sync.aligned.m8n8.x4.shared.b16 {%0,%1,%2,%3}, [%4];"
                         : "=r"(bl0), "=r"(bl1), "=r"(bl2), "=r"(bl3)
                         : "r"(baddr + (uint32_t)BTILE_B));
            float* c0 = acc[2 * ntp];
            float* c1 = acc[2 * ntp + 1];
            mma16816(c0, ah0, ah1, ah2, ah3, bh0, bh1);
            mma16816(c1, ah0, ah1, ah2, ah3, bh2, bh3);
            mma16816(c0, ah0, ah1, ah2, ah3, bl0, bl1);
            mma16816(c1, ah0, ah1, ah2, ah3, bl2, bl3);
            mma16816(c0, al0, al1, al2, al3, bh0, bh1);
            mma16816(c1, al0, al1, al2, al3, bh2, bh3);
        }
    }
}

__device__ __forceinline__ uint32_t split2(float v0, float v1, uint32_t& lo_out) {
    __nv_bfloat16 h0 = __float2bfloat16(v0), h1 = __float2bfloat16(v1);
    __nv_bfloat16 l0 = __float2bfloat16(v0 - __bfloat162float(h0));
    __nv_bfloat16 l1 = __float2bfloat16(v1 - __bfloat162float(h1));
    lo_out = ((uint32_t)__bfloat16_as_ushort(l1) << 16) | __bfloat16_as_ushort(l0);
    return ((uint32_t)__bfloat16_as_ushort(h1) << 16) | __bfloat16_as_ushort(h0);
}

// ---------------- fold BN into W1/b1 ----------------------------------------
__global__ void fold_bn_kernel(const float* __restrict__ W1,
                               const float* __restrict__ b1,
                               const float* __restrict__ gamma,
                               const float* __restrict__ beta,
                               const float* __restrict__ mean,
                               const float* __restrict__ var) {
    int k = blockIdx.x;
    int l = blockIdx.y;
    int c = threadIdx.x;
    float s = rsqrtf(var[l * D + c] + BN_EPS) * gamma[l * D + c];
    g_W1p[(l * D + k) * D + c] = W1[(l * D + k) * D + c] * s;
    if (k == 0)
        g_b1p[l * D + c] = (b1[l * D + c] - mean[l * D + c]) * s + beta[l * D + c];
}

// ---------------- pre-split weights: Wt[n][k] = W[k][n], hi/lo bf16 ----------
__global__ void prep_w_kernel(const float* __restrict__ W2,
                              const float* __restrict__ hW1,
                              const float* __restrict__ hW2) {
    int idx = blockIdx.x * 256 + threadIdx.x;   // 0..16383
    int m = blockIdx.y;                          // 0..7
    int nn = idx & 127;
    int k  = idx >> 7;
    float w;
    if (m < 3)      w = g_W1p[m * D * D + k * D + nn];
    else if (m < 6) w = W2[(m - 3) * D * D + k * D + nn];
    else if (m == 6) w = hW1[k * D + nn];
    else             w = hW2[k * D + nn];
    __nv_bfloat16 hi = __float2bfloat16(w);
    float rem = w - __bfloat162float(hi);
    int off = m * D * D + nn * D + k;           // [mat][n][k]
    g_Wt_hi[off] = hi;
    g_Wt_lo[off] = __float2bfloat16(rem);
}

// ---------------- CSR build --------------------------------------------------
__global__ void zero_deg(int* deg, int n) {
    int i = blockIdx.x * 256 + threadIdx.x;
    if (i < n) deg[i] = 0;
}

__global__ void hist_kernel(const int* __restrict__ ei, int* deg, int nE) {
    int e = blockIdx.x * 256 + threadIdx.x;
    if (e < nE) atomicAdd(&deg[__ldg(ei + nE + e)], 1);
}

__global__ void scan1(const int* __restrict__ deg, int* off, int* bsums, int n) {
    __shared__ int warpsum[16];
    int t = threadIdx.x;
    int i = blockIdx.x * 512 + t;
    int v = (i < n) ? deg[i] : 0;
    int lane = t & 31, w = t >> 5;
    int s = v;
#pragma unroll
    for (int o = 1; o < 32; o <<= 1) {
        int u = __shfl_up_sync(0xffffffffu, s, o);
        if (lane >= o) s += u;
    }
    if (lane == 31) warpsum[w] = s;
    __syncthreads();
    if (w == 0) {
        int ws = (lane < 16) ? warpsum[lane] : 0;
#pragma unroll
        for (int o = 1; o < 16; o <<= 1) {
            int u = __shfl_up_sync(0xffffffffu, ws, o);
            if (lane >= o) ws += u;
        }
        if (lane < 16) warpsum[lane] = ws;
    }
    __syncthreads();
    int base = (w > 0) ? warpsum[w - 1] : 0;
    if (i < n) off[i] = base + s - v;
    if (t == 0) bsums[blockIdx.x] = warpsum[15];
}

__global__ void scan2(int* bsums, int nb) {
    __shared__ int ws[8];
    int t = threadIdx.x, lane = t & 31, w = t >> 5;
    int v = (t < nb) ? bsums[t] : 0;
    int s = v;
#pragma unroll
    for (int o = 1; o < 32; o <<= 1) {
        int u = __shfl_up_sync(0xffffffffu, s, o);
        if (lane >= o) s += u;
    }
    if (lane == 31) ws[w] = s;
    __syncthreads();
    if (w == 0 && lane < 8) {
        int a = ws[lane];
#pragma unroll
        for (int o = 1; o < 8; o <<= 1) {
            int u = __shfl_up_sync(0xffu, a, o);
            if (lane >= o) a += u;
        }
        ws[lane] = a;
    }
    __syncthreads();
    int base = (w > 0) ? ws[w - 1] : 0;
    if (t < nb) bsums[t] = base + s - v;
}

__global__ void scan3(int* off, const int* __restrict__ bsums, int* cur, int n, int nE) {
    int i = blockIdx.x * 256 + threadIdx.x;
    if (i < n) {
        int v = off[i] + bsums[i >> 9];
        off[i] = v;
        cur[i] = v;
    }
    if (i == 0) off[n] = nE;
}

__global__ void fill_csr(const int* __restrict__ ei, int* cur, int* col, int nE) {
    int e = blockIdx.x * 256 + threadIdx.x;
    if (e >= nE) return;
    int s = __ldg(ei + e);
    int d = __ldg(ei + nE + e);
    int p = atomicAdd(&cur[d], 1);
    col[p] = s;
}

// ---------------- aggregation: agg[i] = x[i] + sum_{j in N(i)} x[j] ---------
__global__ void gather_agg(const float* __restrict__ x,
                           const int* __restrict__ off,
                           const int* __restrict__ col,
                           float* __restrict__ agg, int n) {
    int node = blockIdx.x * 8 + (threadIdx.x >> 5);
    if (node >= n) return;
    int lane = threadIdx.x & 31;
    int beg = __ldg(off + node), end = __ldg(off + node + 1);
    float4 acc = __ldg((const float4*)x + (long long)node * 32 + lane);
    int e = beg;
    for (; e + 3 < end; e += 4) {
        int s0 = __ldg(col + e), s1 = __ldg(col + e + 1);
        int s2 = __ldg(col + e + 2), s3 = __ldg(col + e + 3);
        float4 v0 = __ldg((const float4*)x + (long long)s0 * 32 + lane);
        float4 v1 = __ldg((const float4*)x + (long long)s1 * 32 + lane);
        float4 v2 = __ldg((const float4*)x + (long long)s2 * 32 + lane);
        float4 v3 = __ldg((const float4*)x + (long long)s3 * 32 + lane);
        acc.x += v0.x + v1.x + v2.x + v3.x;
        acc.y += v0.y + v1.y + v2.y + v3.y;
        acc.z += v0.z + v1.z + v2.z + v3.z;
        acc.w += v0.w + v1.w + v2.w + v3.w;
    }
    for (; e < end; e++) {
        int s0 = __ldg(col + e);
        float4 v0 = __ldg((const float4*)x + (long long)s0 * 32 + lane);
        acc.x += v0.x; acc.y += v0.y; acc.z += v0.z; acc.w += v0.w;
    }
    ((float4*)agg)[(long long)node * 32 + lane] = acc;
}

// ---------------- pooling (batch is sorted -> segmented reduction) ----------
__global__ void zero_kernel(float4* __restrict__ p, int n4) {
    int i = blockIdx.x * blockDim.x + threadIdx.x;
    if (i < n4) p[i] = make_float4(0.f, 0.f, 0.f, 0.f);
}

__global__ void pool_nodes(const float* __restrict__ x,
                           const int* __restrict__ batch,
                           float* __restrict__ g, int n) {
    int w = blockIdx.x * 8 + (threadIdx.x >> 5);   // warp id: 8 nodes each
    int lane = threadIdx.x & 31;
    int i0 = w * 8;
    if (i0 >= n) return;
    int iend = min(i0 + 8, n);
    int curb = __ldg(batch + i0);
    float4 acc = make_float4(0.f, 0.f, 0.f, 0.f);
    for (int i = i0; i < iend; i++) {
        int b = __ldg(batch + i);
        if (b != curb) {
            const float4* dp = (const float4*)g + (long long)curb * 32 + lane;
            asm volatile("red.global.add.v4.f32 [%0], {%1, %2, %3, %4};"
                         :: "l"(dp), "f"(acc.x), "f"(acc.y), "f"(acc.z), "f"(acc.w)
                         : "memory");
            acc = make_float4(0.f, 0.f, 0.f, 0.f);
            curb = b;
        }
        float4 v = __ldg((const float4*)x + (long long)i * 32 + lane);
        acc.x += v.x; acc.y += v.y; acc.z += v.z; acc.w += v.w;
    }
    const float4* dp = (const float4*)g + (long long)curb * 32 + lane;
    asm volatile("red.global.add.v4.f32 [%0], {%1, %2, %3, %4};"
                 :: "l"(dp), "f"(acc.x), "f"(acc.y), "f"(acc.z), "f"(acc.w)
                 : "memory");
}

// ---------------- fused GEMM pair: C = relu(relu(A@W1+b1)@W2+b2) ------------
// BM=64 rows, 128 threads, 2 CTAs/SM -> staging of one CTA overlaps MMA of other
__global__ __launch_bounds__(128, 2) void gemm_pair(
    const float* __restrict__ A, int mat1, int mat2,
    const float* __restrict__ bias1, const float* __restrict__ bias2,
    float* __restrict__ C, int n) {
    extern __shared__ char smp[];
    uint32_t base = smem_u32(smp);
    int t = threadIdx.x;
    int wid = t >> 5;
    int lane = t & 31;
    int row0 = blockIdx.x * 64;
    int m0 = wid * 16;

    // stage A (f32 -> split bf16): 64 rows x 32 float4 = 2048
#pragma unroll
    for (int it = 0; it < 16; it++) {
        int idx = it * 128 + t;
        int row = idx >> 5;
        int k4 = idx & 31;
        float4 v = make_float4(0.f, 0.f, 0.f, 0.f);
        if (row0 + row < n) v = __ldg((const float4*)A + (long long)(row0 + row) * 32 + k4);
        uint2 hp, lp;
        hp.x = split2(v.x, v.y, lp.x);
        hp.y = split2(v.z, v.w, lp.y);
        int off = row * (PITCH * 2) + k4 * 8;
        *(uint2*)(smp + SA_HI + off) = hp;
        *(uint2*)(smp + SA_LO + off) = lp;
    }
    stage_W(smp, mat1, t);
    if (t < 32) {
        ((float4*)(smp + S_B1))[t] = __ldg((const float4*)bias1 + t);
        ((float4*)(smp + S_B2))[t] = __ldg((const float4*)bias2 + t);
    }
    __syncthreads();

    // MMA1
    float acc[16][4];
    do_mma(base, lane, m0, acc);
    __syncthreads();

    // h1 = relu(acc + bias1) -> re-split into SA;  restage W2
    {
        const float* b1s = (const float*)(smp + S_B1);
        int rA = m0 + (lane >> 2);
        int cq = (lane & 3) * 2;
#pragma unroll
        for (int nt = 0; nt < 16; nt++) {
            int cl = nt * 8 + cq;
            float b0 = b1s[cl], b1v = b1s[cl + 1];
            float v0 = fmaxf(acc[nt][0] + b0, 0.f), v1 = fmaxf(acc[nt][1] + b1v, 0.f);
            float v2 = fmaxf(acc[nt][2] + b0, 0.f), v3 = fmaxf(acc[nt][3] + b1v, 0.f);
            uint32_t lo0, lo1;
            uint32_t hi0 = split2(v0, v1, lo0);
            uint32_t hi1 = split2(v2, v3, lo1);
            int o0 = rA * (PITCH * 2) + cl * 2;
            int o1 = (rA + 8) * (PITCH * 2) + cl * 2;
            *(uint32_t*)(smp + SA_HI + o0) = hi0;
            *(uint32_t*)(smp + SA_LO + o0) = lo0;
            *(uint32_t*)(smp + SA_HI + o1) = hi1;
            *(uint32_t*)(smp + SA_LO + o1) = lo1;
        }
    }
    stage_W(smp, mat2, t);
    __syncthreads();

    // MMA2
    do_mma(base, lane, m0, acc);

    // epilogue: out = relu(acc + bias2)
    {
        const float* b2s = (const float*)(smp + S_B2);
        int r0 = row0 + m0 + (lane >> 2);
        int cq = (lane & 3) * 2;
#pragma unroll
        for (int nt = 0; nt < 16; nt++) {
            int cl = nt * 8 + cq;
            float b0 = b2s[cl], b1v = b2s[cl + 1];
            float2 v0 = make_float2(fmaxf(acc[nt][0] + b0, 0.f), fmaxf(acc[nt][1] + b1v, 0.f));
            float2 v1 = make_float2(fmaxf(acc[nt][2] + b0, 0.f), fmaxf(acc[nt][3] + b1v, 0.f));
            if (r0 < n)     *(float2*)(C + (long long)r0 * D + cl) = v0;
            if (r0 + 8 < n) *(float2*)(C + (long long)(r0 + 8) * D + cl) = v1;
        }
    }
}

// ---------------- standalone mma GEMM (head), BM=64, 128 threads ------------
__global__ __launch_bounds__(128, 2) void gemm_tc(
    const float* __restrict__ A, int mat,
    const float* __restrict__ bias, float* __restrict__ C, int n, int relu) {
    extern __shared__ char smp[];
    uint32_t base = smem_u32(smp);
    int t = threadIdx.x;
    int wid = t >> 5;
    int lane = t & 31;
    int row0 = blockIdx.x * 64;

#pragma unroll
    for (int it = 0; it < 16; it++) {
        int idx = it * 128 + t;
        int row = idx >> 5;
        int k4 = idx & 31;
        float4 v = make_float4(0.f, 0.f, 0.f, 0.f);
        if (row0 + row < n) v = __ldg((const float4*)A + (long long)(row0 + row) * 32 + k4);
        uint2 hp, lp;
        hp.x = split2(v.x, v.y, lp.x);
        hp.y = split2(v.z, v.w, lp.y);
        int off = row * (PITCH * 2) + k4 * 8;
        *(uint2*)(smp + SA_HI + off) = hp;
        *(uint2*)(smp + SA_LO + off) = lp;
    }
    stage_W(smp, mat, t);
    if (t < 32) ((float4*)(smp + S_B1))[t] = __ldg((const float4*)bias + t);
    __syncthreads();

    float acc[16][4];
    do_mma(base, lane, wid * 16, acc);

    const float* bias_s = (const float*)(smp + S_B1);
    int r0 = row0 + wid * 16 + (lane >> 2);
    int cq = (lane & 3) * 2;
#pragma unroll
    for (int nt = 0; nt < 16; nt++) {
        int cl = nt * 8 + cq;
        float b0 = bias_s[cl], b1v = bias_s[cl + 1];
        float2 v0 = make_float2(acc[nt][0] + b0, acc[nt][1] + b1v);
        float2 v1 = make_float2(acc[nt][2] + b0, acc[nt][3] + b1v);
        if (relu) {
            v0.x = fmaxf(v0.x, 0.f); v0.y = fmaxf(v0.y, 0.f);
            v1.x = fmaxf(v1.x, 0.f); v1.y = fmaxf(v1.y, 0.f);
        }
        if (r0 < n)     *(float2*)(C + (long long)r0 * D + cl) = v0;
        if (r0 + 8 < n) *(float2*)(C + (long long)(r0 + 8) * D + cl) = v1;
    }
}

// ---------------- launch -----------------------------------------------------
extern "C" void kernel_launch(void* const* d_in, const int* in_sizes, int n_in,
                              void* d_out, int out_size) {
    const float* x        = (const float*)d_in[0];
    const int*   ei       = (const int*)d_in[1];      // int32 (JAX x64 disabled)
    const int*   batch    = (const int*)d_in[2];      // int32
    const float* W1       = (const float*)d_in[3];
    const float* b1       = (const float*)d_in[4];
    const float* gamma    = (const float*)d_in[5];
    const float* beta     = (const float*)d_in[6];
    const float* mean     = (const float*)d_in[7];
    const float* var      = (const float*)d_in[8];
    const float* W2       = (const float*)d_in[9];
    const float* b2       = (const float*)d_in[10];
    const float* hW1      = (const float*)d_in[11];
    const float* hb1      = (const float*)d_in[12];
    const float* hW2      = (const float*)d_in[13];
    const float* hb2      = (const float*)d_in[14];

    int n  = in_sizes[0] / D;
    int nE = in_sizes[1] / 2;

    float *agg, *xa, *xb, *b1p, *pool, *hid;
    int *deg, *off, *cur, *col, *bsums;
    cudaGetSymbolAddress((void**)&agg,  g_agg);
    cudaGetSymbolAddress((void**)&xa,   g_xa);
    cudaGetSymbolAddress((void**)&xb,   g_xb);
    cudaGetSymbolAddress((void**)&b1p,  g_b1p);
    cudaGetSymbolAddress((void**)&pool, g_pool);
    cudaGetSymbolAddress((void**)&hid,  g_hid);
    cudaGetSymbolAddress((void**)&deg,  g_deg);
    cudaGetSymbolAddress((void**)&off,  g_off);
    cudaGetSymbolAddress((void**)&cur,  g_cur);
    cudaGetSymbolAddress((void**)&col,  g_col);
    cudaGetSymbolAddress((void**)&bsums, g_bsums);

    cudaFuncSetAttribute(gemm_pair, cudaFuncAttributeMaxDynamicSharedMemorySize, GEMM_SMEM);
    cudaFuncSetAttribute(gemm_tc, cudaFuncAttributeMaxDynamicSharedMemorySize, GEMM_SMEM);

    int gemmGrid = (n + 63) / 64;
    int nb = (n + 511) / 512;

    // prep: BN fold, weight split, CSR build
    fold_bn_kernel<<<dim3(D, 3), D>>>(W1, b1, gamma, beta, mean, var);
    prep_w_kernel<<<dim3(64, 8), 256>>>(W2, hW1, hW2);
    zero_deg<<<(n + 255) / 256, 256>>>(deg, n);
    hist_kernel<<<(nE + 255) / 256, 256>>>(ei, deg, nE);
    scan1<<<nb, 512>>>(deg, off, bsums, n);
    scan2<<<1, 256>>>(bsums, nb);
    scan3<<<(n + 255) / 256, 256>>>(off, bsums, cur, n, nE);
    fill_csr<<<(nE + 255) / 256, 256>>>(ei, cur, col, nE);

    const float* xin = x;
    float* outs[3] = {xa, xb, xa};
    for (int l = 0; l < 3; l++) {
        gather_agg<<<(n + 7) / 8, 256>>>(xin, off, col, agg, n);
        gemm_pair<<<gemmGrid, 128, GEMM_SMEM>>>(agg, l, 3 + l,
                                                b1p + l * D, b2 + l * D,
                                                outs[l], n);
        xin = outs[l];
    }

    zero_kernel<<<(NG * 32 + 255) / 256, 256>>>((float4*)pool, NG * 32);
    pool_nodes<<<(n + 63) / 64, 256>>>(xin, batch, pool, n);
    gemm_tc<<<NG / 64, 128, GEMM_SMEM>>>(pool, 6, hb1, hid, NG, 1);
    gemm_tc<<<NG / 64, 128, GEMM_SMEM>>>(hid, 7, hb2, (float*)d_out, NG, 0);
}